// round 15
// baseline (speedup 1.0000x reference)
#include <cuda_runtime.h>
#include <cuda_bf16.h>
#include <cuda_fp16.h>
#include <cstdint>

// Problem constants
#define NB   16
#define TT   2048
#define FIN  64
#define NN   24
#define HH   64
#define BT   (NB*TT)            // 32768
#define NH   (NN*HH)            // 1536
#define TOK  16                 // tokens per tile
#define THR  512
#define NTILE (BT/TOK)          // 2048
#define PGRID 152               // persistent blocks
#define ALPHA 0.2f
#define NEGINF (-9.0e15f)
#define XS3  68                 // token-major sX row stride

// ---------------- device globals (no allocs) ----------------
__device__ __align__(16) float g_Wc[FIN*NH];    // [f][col], col = n*64+k
__device__ __align__(16) float g_bc[NH];
__device__ __align__(16) float g_ca1[FIN*NN];
__device__ __align__(16) float g_ca2[FIN*NN];
__device__ float g_cb1[NN];
__device__ float g_cb2[NN];
// B fragments for mma.m16n8k16 fp16, single term, fragment-ordered:
// index = (ct*4 + ks)*32 + lane, each 8B = {b0, b1}
__device__ __align__(16) unsigned long long g_Wfrag[192*4*32];   // 192KB

// ---------------- packed fp32x2 helpers ----------------
__device__ __forceinline__ unsigned long long pack2(float lo, float hi) {
    unsigned long long r;
    asm("mov.b64 %0, {%1, %2};" : "=l"(r) : "f"(lo), "f"(hi));
    return r;
}
__device__ __forceinline__ void unpack2u(unsigned long long v, uint32_t& lo, uint32_t& hi) {
    asm("mov.b64 {%0, %1}, %2;" : "=r"(lo), "=r"(hi) : "l"(v));
}
__device__ __forceinline__ void unpack2(unsigned long long v, float& lo, float& hi) {
    asm("mov.b64 {%0, %1}, %2;" : "=f"(lo), "=f"(hi) : "l"(v));
}
#define FMA2(acc, a, b) asm("fma.rn.f32x2 %0, %1, %2, %0;" : "+l"(acc) : "l"(a), "l"(b))

// ---------------- warp mma m16n8k16 fp16 (f32 accum) ----------------
__device__ __forceinline__ void mma16816(float& d0, float& d1, float& d2, float& d3,
                                         uint32_t a0, uint32_t a1, uint32_t a2, uint32_t a3,
                                         uint32_t b0, uint32_t b1) {
    asm("mma.sync.aligned.m16n8k16.row.col.f32.f16.f16.f32 "
        "{%0,%1,%2,%3}, {%4,%5,%6,%7}, {%8,%9}, {%0,%1,%2,%3};"
        : "+f"(d0), "+f"(d1), "+f"(d2), "+f"(d3)
        : "r"(a0), "r"(a1), "r"(a2), "r"(a3), "r"(b0), "r"(b1));
}
__device__ __forceinline__ uint32_t hpack(__half x, __half y) {
    __half2 p; p.x = x; p.y = y;
    return *(uint32_t*)&p;
}

// ---------------- cp.async ----------------
__device__ __forceinline__ uint32_t smem_u32(const void* p) {
    return (uint32_t)__cvta_generic_to_shared(p);
}
#define CP_ASYNC16(dst, src) \
    asm volatile("cp.async.cg.shared.global [%0], [%1], 16;" :: "r"(dst), "l"(src) : "memory")
#define CP_COMMIT() asm volatile("cp.async.commit_group;" ::: "memory")
#define CP_WAIT1()  asm volatile("cp.async.wait_group 1;" ::: "memory")
#define BAR384()    asm volatile("bar.sync 1, 384;" ::: "memory")

// ---------------- precompute: grid (64, 4) ----------------
__global__ void __launch_bounds__(256)
k_pre(const float* __restrict__ Wp, const float* __restrict__ bp,
      const float* __restrict__ W,  const float* __restrict__ a) {
    __shared__ float sW[HH*HH];
    __shared__ float sWp[NH];
    __shared__ float swa1[HH], swa2[HH];
    const int f = blockIdx.x, q = blockIdx.y, tid = threadIdx.x;
    for (int i = tid; i < HH*HH; i += 256) sW[i] = W[i];
    for (int i = tid; i < NH;    i += 256) sWp[i] = Wp[f*NH + i];
    __syncthreads();
    if (q == 0 && tid < HH) {
        float s1 = 0.f, s2 = 0.f, s3 = 0.f, s4 = 0.f;
        #pragma unroll
        for (int k = 0; k < HH; k += 2) {
            float w0 = sW[tid*HH + k], w1 = sW[tid*HH + k + 1];
            s1 = fmaf(w0, a[k],        s1);
            s3 = fmaf(w1, a[k+1],      s3);
            s2 = fmaf(w0, a[HH+k],     s2);
            s4 = fmaf(w1, a[HH+k+1],   s4);
        }
        swa1[tid] = s1 + s3; swa2[tid] = s2 + s4;
    }
    __syncthreads();
    for (int o = q*384 + tid; o < q*384 + 384; o += 256) {
        int n = o >> 6, k = o & 63;
        float s0 = 0.f, s1 = 0.f, s2 = 0.f, s3 = 0.f;
        #pragma unroll
        for (int j = 0; j < HH; j += 4) {
            s0 = fmaf(sWp[n*HH + j],     sW[(j)*HH + k],   s0);
            s1 = fmaf(sWp[n*HH + j + 1], sW[(j+1)*HH + k], s1);
            s2 = fmaf(sWp[n*HH + j + 2], sW[(j+2)*HH + k], s2);
            s3 = fmaf(sWp[n*HH + j + 3], sW[(j+3)*HH + k], s3);
        }
        g_Wc[f*NH + o] = (s0 + s1) + (s2 + s3);
    }
    if (q == 0) {
        if (tid < NN) {
            float s1 = 0.f, s2 = 0.f, s3 = 0.f, s4 = 0.f;
            #pragma unroll
            for (int j = 0; j < HH; j += 2) {
                float w0 = sWp[tid*HH + j], w1 = sWp[tid*HH + j + 1];
                s1 = fmaf(w0, swa1[j],   s1);
                s3 = fmaf(w1, swa1[j+1], s3);
                s2 = fmaf(w0, swa2[j],   s2);
                s4 = fmaf(w1, swa2[j+1], s4);
            }
            g_ca1[f*NN + tid] = s1 + s3;
            g_ca2[f*NN + tid] = s2 + s4;
        }
        if (tid >= 32 && tid < 32 + NN) {
            int c = f*NN + (tid - 32);
            int n = c >> 6, k = c & 63;
            float s0 = 0.f, s1 = 0.f;
            #pragma unroll
            for (int j = 0; j < HH; j += 2) {
                s0 = fmaf(bp[n*HH + j],     sW[(j)*HH + k],   s0);
                s1 = fmaf(bp[n*HH + j + 1], sW[(j+1)*HH + k], s1);
            }
            g_bc[c] = s0 + s1;
        }
        if (f == 0 && tid >= 64 && tid < 64 + NN) {
            int n = tid - 64;
            float s1 = 0.f, s2 = 0.f;
            for (int j = 0; j < HH; j++) {
                float b = bp[n*HH + j];
                s1 = fmaf(b, swa1[j], s1);
                s2 = fmaf(b, swa2[j], s2);
            }
            g_cb1[n] = s1; g_cb2[n] = s2;
        }
    }
}

// ---------------- B-fragment precompute: single fp16 term ----------------
__global__ void k_frag() {
    int u = blockIdx.x * 256 + threadIdx.x;
    if (u >= 192*4*32) return;
    int lane = u & 31;
    int ks   = (u >> 5) & 3;
    int ct   = u >> 7;
    int col = ct*8 + (lane >> 2);
    int f0  = ks*16 + (lane & 3)*2;
    __half e[4];
    #pragma unroll
    for (int r = 0; r < 4; r++) {
        int f = f0 + (r >> 1)*8 + (r & 1);
        e[r] = __float2half(g_Wc[f*NH + col]);
    }
    uint32_t b0 = hpack(e[0], e[1]);
    uint32_t b1 = hpack(e[2], e[3]);
    g_Wfrag[u] = ((unsigned long long)b1 << 32) | b0;
}

// ---------------- persistent fused kernel, cross-tile pipelined ----------------
// smem (bytes):
//  sXa    @ 0      : 16x68 f32                         4608
//  sXb    @ 4608   : 16x68 f32                         4608
//  sCa1   @ 9216   : 1536 f32                          6144
//  sCa2   @ 15360  : 1536 f32                          6144
//  sCb1   @ 21504  : 24 f32                            96
//  sCb2   @ 21600  : 24 f32                            96
//  sF1    @ 21696  : 384 f32                           1536
//  sF2    @ 23232  : 384 f32                           1536
//  sAdj   @ 24768  : 576 i32                           2304
//  sAttn0 @ 27072  : 16x576 f32                        36864
//  sAttn1 @ 63936  : 16x576 f32                        36864
//  sWh0   @ 100800 : 16x1536 fp16                      49152
//  sWh1   @ 149952 : 16x1536 fp16                      49152
//  sBC    @ 199104 : 1536 f32                          6144
#define SMEM_BYTES 205248

__global__ void __launch_bounds__(THR, 1)
k_main(const float* __restrict__ x, const int* __restrict__ adj,
       float* __restrict__ out) {
    extern __shared__ char smem[];
    float*  sXbuf[2]  = { (float*)(smem), (float*)(smem + 4608) };
    float*  sCa1  = (float*)(smem + 9216);
    float*  sCa2  = (float*)(smem + 15360);
    float*  sCb1  = (float*)(smem + 21504);
    float*  sCb2  = (float*)(smem + 21600);
    float*  sF1   = (float*)(smem + 21696);
    float*  sF2   = (float*)(smem + 23232);
    int*    sAdj  = (int*)  (smem + 24768);
    float*  sAttnB[2] = { (float*)(smem + 27072), (float*)(smem + 63936) };
    __half* sWhB[2]   = { (__half*)(smem + 100800), (__half*)(smem + 149952) };
    float*  sBC   = (float*)(smem + 199104);

    const int tid = threadIdx.x;
    const int w = tid >> 5, lane = tid & 31;

    // ---- one-time loads ----
    for (int i = tid; i < FIN*NN; i += THR) { sCa1[i] = g_ca1[i]; sCa2[i] = g_ca2[i]; }
    for (int i = tid; i < NH;     i += THR) sBC[i] = g_bc[i];
    if (tid < NN) { sCb1[tid] = g_cb1[tid]; sCb2[tid] = g_cb2[tid]; }
    for (int i = tid; i < NN*NN; i += THR) sAdj[i] = adj[i];

    auto prefetch_sX = [&](float* dst, int tile) {
        if (tile < NTILE && tid < 256) {
            int t = tid >> 4, c = tid & 15;
            CP_ASYNC16(smem_u32(dst + t*XS3 + c*4),
                       x + (size_t)(tile*TOK + t)*FIN + c*4);
        }
        CP_COMMIT();
    };

    // phase-2: attn(prev) @ Wh(prev), elu, mean -> out   (warp = token)
    auto phase2 = [&](int ptok0, int pb) {
        const int t = w;
        const int g = lane;                    // k in {g, g+32}
        const __half* whb = sWhB[pb] + (size_t)t*NH;
        unsigned long long wj[12][2];
        #pragma unroll
        for (int m = 0; m < 12; m++) {
            wj[m][0] = pack2(__half2float(whb[(2*m)*HH + g]),
                             __half2float(whb[(2*m+1)*HH + g]));
            wj[m][1] = pack2(__half2float(whb[(2*m)*HH + g + 32]),
                             __half2float(whb[(2*m+1)*HH + g + 32]));
        }
        const unsigned long long* ap = (const unsigned long long*)(sAttnB[pb] + t*576);
        float o0 = 0.f, o1 = 0.f;
        #pragma unroll 2
        for (int i = 0; i < NN; i++) {
            unsigned long long s0 = 0ull, s1 = 0ull;
            #pragma unroll
            for (int m = 0; m < 12; m++) {
                unsigned long long av = ap[i*12 + m];
                FMA2(s0, av, wj[m][0]);
                FMA2(s1, av, wj[m][1]);
            }
            float a0, b0, a1, b1;
            unpack2(s0, a0, b0);
            unpack2(s1, a1, b1);
            float v0 = a0 + b0, v1 = a1 + b1;
            o0 += (v0 > 0.f) ? v0 : (__expf(v0) - 1.f);
            o1 += (v1 > 0.f) ? v1 : (__expf(v1) - 1.f);
        }
        const float sc = 1.0f / (float)NN;
        float* ob = out + (size_t)(ptok0 + t) * HH;
        ob[g]      = o0 * sc;
        ob[g + 32] = o1 * sc;
    };

    int tile = blockIdx.x;
    int b = 0, wb = 0;
    int prev_tok0 = -1;
    prefetch_sX(sXbuf[0], tile);

    for (; tile < NTILE; tile += PGRID) {
        // sync A: ALL warps finished prior iteration (incl. phase-2(prev-1) reads of
        // sWh/sAttn[wb] and all reads of sXbuf[b^1]) -> safe to prefetch + overwrite.
        __syncthreads();
        prefetch_sX(sXbuf[b ^ 1], tile + PGRID);
        CP_WAIT1();
        __syncthreads();   // sync B: sXbuf[b] visible to all threads
        const float* sX = sXbuf[b];
        float* sAttn = sAttnB[wb];
        __half* sWh  = sWhB[wb];

        // ---- f1/f2 (warps 0-11) ----
        if (tid < TOK*NN) {
            int t = tid / NN, n = tid % NN;
            float s1 = sCb1[n], s2 = sCb2[n];
            #pragma unroll 8
            for (int f = 0; f < FIN; f++) {
                float xv = sX[t*XS3 + f];
                s1 = fmaf(xv, sCa1[f*NN + n], s1);
                s2 = fmaf(xv, sCa2[f*NN + n], s2);
            }
            sF1[t*NN + n] = s1;
            sF2[t*NN + n] = s2;
            BAR384();
            // ---- softmax rows -> sAttn[wb] ----
            int i = n;
            float f1v = s1;
            float ev[NN];
            float m = -3.0e38f;
            #pragma unroll
            for (int j = 0; j < NN; j++) {
                float e = f1v + sF2[t*NN + j];
                e = e > 0.f ? e : ALPHA * e;
                e = (sAdj[i*NN + j] > 0) ? e : NEGINF;
                ev[j] = e;
                m = fmaxf(m, e);
            }
            float sum = 0.f;
            #pragma unroll
            for (int j = 0; j < NN; j++) { float p = __expf(ev[j] - m); ev[j] = p; sum += p; }
            float inv = 1.0f / sum;
            #pragma unroll
            for (int j = 0; j < NN; j++) sAttn[t*576 + i*NN + j] = ev[j] * inv;
        }

        // ---- phase 1: Wh = x @ Wc + bc -> sWh[wb] (fp16), rebalanced nt ----
        {
            const int t0 = lane >> 2;
            const int fq = (lane & 3) * 2;
            int ctb, cnt;
            if (w < 12) { ctb = w*10;              cnt = 10; }
            else        { ctb = 120 + (w-12)*18;   cnt = 18; }

            uint32_t ah[4][4], al[4][4];
            #pragma unroll
            for (int ks = 0; ks < 4; ks++) {
                #pragma unroll
                for (int r = 0; r < 4; r++) {
                    int f = ks*16 + fq + (r >> 1)*8;
                    int t = t0 + (r & 1)*8;
                    float2 v = *(const float2*)&sX[t*XS3 + f];
                    __half h0 = __float2half(v.x);
                    __half h1 = __float2half(v.y);
                    ah[ks][r] = hpack(h0, h1);
                    al[ks][r] = hpack(__float2half(v.x - __half2float(h0)),
                                      __float2half(v.y - __half2float(h1)));
                }
            }

            unsigned long long fb[2][4];
            #pragma unroll
            for (int ks = 0; ks < 4; ks++)
                fb[0][ks] = __ldg(&g_Wfrag[(ctb*4 + ks)*32 + lane]);
            for (int nt = 0; nt < cnt; nt++) {
                const int cb = nt & 1, pb = cb ^ 1;
                if (nt + 1 < cnt) {
                    const int ct2 = ctb + nt + 1;
                    #pragma unroll
                    for (int ks = 0; ks < 4; ks++)
                        fb[pb][ks] = __ldg(&g_Wfrag[(ct2*4 + ks)*32 + lane]);
                }
                float d0 = 0.f, d1 = 0.f, d2 = 0.f, d3 = 0.f;
                #pragma unroll
                for (int ks = 0; ks < 4; ks++) {
                    uint32_t b0, b1;
                    unpack2u(fb[cb][ks], b0, b1);
                    mma16816(d0, d1, d2, d3, ah[ks][0], ah[ks][1], ah[ks][2], ah[ks][3], b0, b1);
                    mma16816(d0, d1, d2, d3, al[ks][0], al[ks][1], al[ks][2], al[ks][3], b0, b1);
                }
                const int col = (ctb + nt)*8 + fq;
                float b0c = sBC[col], b1c = sBC[col + 1];
                *(__half2*)&sWh[t0*NH + col]     = __floats2half2_rn(d0 + b0c, d1 + b1c);
                *(__half2*)&sWh[(t0+8)*NH + col] = __floats2half2_rn(d2 + b0c, d3 + b1c);
            }
        }

        // ---- phase 2 for PREVIOUS tile (reads buffers wb^1; no barrier needed:
        //      sWh/sAttn[wb^1] were completed last iteration, ordered by sync A) ----
        if (prev_tok0 >= 0) phase2(prev_tok0, wb ^ 1);

        prev_tok0 = tile * TOK;
        b ^= 1; wb ^= 1;
    }

    // drain: final tile's phase-2 (its buffers are wb^1 after the last flip)
    __syncthreads();
    if (prev_tok0 >= 0) phase2(prev_tok0, wb ^ 1);
}

// ---------------- launch ----------------
extern "C" void kernel_launch(void* const* d_in, const int* in_sizes, int n_in,
                              void* d_out, int out_size) {
    const float* x   = (const float*)d_in[0];
    const int*   adj = (const int*)  d_in[1];
    const float* Wp  = (const float*)d_in[2];
    const float* bp  = (const float*)d_in[3];
    const float* W   = (const float*)d_in[4];
    const float* a   = (const float*)d_in[5];
    float* out = (float*)d_out;

    k_pre<<<dim3(FIN, 4), 256>>>(Wp, bp, W, a);
    k_frag<<<96, 256>>>();

    cudaFuncSetAttribute(k_main, cudaFuncAttributeMaxDynamicSharedMemorySize, SMEM_BYTES);
    k_main<<<PGRID, THR, SMEM_BYTES>>>(x, adj, out);
}